// round 13
// baseline (speedup 1.0000x reference)
#include <cuda_runtime.h>
#include <cuda_bf16.h>
#include <math.h>
#include <stdint.h>

#define BATCH 256
#define CIN   32
#define HW    1024          // 32x32
#define P     192
#define COUT  32
#define NPIX  (BATCH*HW)    // 262144
#define EPSV  1e-5

// ---------------- scratch (device globals; no allocations allowed) ----------
__device__ float  g_out1[P*NPIX];        // layer1 raw conv output [p][b*1024+s]
__device__ float  g_out2[P*NPIX];        // layer2 raw conv output
__device__ float  g_out3[COUT*NPIX];     // layer3 raw conv output
__device__ unsigned char g_W1img[147456]; // [hi | mid | lo] (raw residuals) 192ch x 256B rows
__device__ unsigned char g_W3img[147456]; // [kc 0..5][hi|mid|lo] 32ch x 256B rows
__device__ float  g_W2[4*P*9];           // eff W2 / n_j, [j][p][9]
__device__ float  g_maxes[48];
__device__ float  g_probs[48];
__device__ double g_sum1[P],  g_ss1[P];
__device__ double g_sum2[P],  g_ss2[P];
__device__ double g_sum3[COUT], g_ss3[COUT];
__device__ float  g_scale1[P], g_shift1[P];
__device__ float  g_scale2[P], g_shift2[P];
__device__ float  g_scale3[COUT], g_shift3[COUT];

__device__ __forceinline__ float quant_round(float v, float n) {
    // match jnp.round(v*n): fp32 multiply (RN), then round-half-even via magic add
    const float MAGIC = 12582912.0f;     // 1.5 * 2^23
    float t = __fmul_rn(v, n);
    return __fsub_rn(__fadd_rn(t, MAGIC), MAGIC);
}

__device__ __forceinline__ unsigned short bf16u(float f) {
    __nv_bfloat16 h = __float2bfloat16(f);
    return *reinterpret_cast<unsigned short*>(&h);
}
__device__ __forceinline__ float bf16f(float f) {
    return __bfloat162float(__float2bfloat16(f));
}

// swizzle within a 256-byte row: XOR the 16B-unit index with (row & 7)
__device__ __forceinline__ uint32_t swz(uint32_t byteInRow, uint32_t row) {
    return ((((byteInRow >> 4) ^ (row & 7u)) << 4) | (byteInRow & 15u));
}

// ---------------- mma.sync / ldmatrix helpers (compute_100-legal) -----------
__device__ __forceinline__ uint32_t smem_u32(const void* p) {
    uint32_t a;
    asm("{ .reg .u64 t; cvta.to.shared.u64 t, %1; cvt.u32.u64 %0, t; }" : "=r"(a) : "l"(p));
    return a;
}
__device__ __forceinline__ void ldm_x4(uint32_t& r0, uint32_t& r1, uint32_t& r2, uint32_t& r3,
                                       uint32_t addr) {
    asm volatile("ldmatrix.sync.aligned.m8n8.x4.shared.b16 {%0,%1,%2,%3}, [%4];"
                 : "=r"(r0), "=r"(r1), "=r"(r2), "=r"(r3) : "r"(addr));
}
__device__ __forceinline__ void ldm_x2(uint32_t& r0, uint32_t& r1, uint32_t addr) {
    asm volatile("ldmatrix.sync.aligned.m8n8.x2.shared.b16 {%0,%1}, [%2];"
                 : "=r"(r0), "=r"(r1) : "r"(addr));
}
#define MMA16816(C, a0, a1, a2, a3, b0, b1) \
    asm volatile("mma.sync.aligned.m16n8k16.row.col.f32.bf16.bf16.f32 " \
                 "{%0,%1,%2,%3}, {%4,%5,%6,%7}, {%8,%9}, {%0,%1,%2,%3};" \
                 : "+f"((C)[0]), "+f"((C)[1]), "+f"((C)[2]), "+f"((C)[3]) \
                 : "r"(a0), "r"(a1), "r"(a2), "r"(a3), "r"(b0), "r"(b1))

// ---------------- K0: zero stats + softmax --------------------------------
__global__ void k_init(const float* __restrict__ p1, const float* __restrict__ p2,
                       const float* __restrict__ p3) {
    int tid = threadIdx.x;
    if (tid < P)    { g_sum1[tid]=0.0; g_ss1[tid]=0.0; g_sum2[tid]=0.0; g_ss2[tid]=0.0; }
    if (tid < COUT) { g_sum3[tid]=0.0; g_ss3[tid]=0.0; }
    if (tid < 3) {
        const float* pp = (tid==0) ? p1 : ((tid==1) ? p2 : p3);
        float mx = -1e30f;
        for (int i=0;i<16;i++) mx = fmaxf(mx, pp[i]);
        float e[16]; float s = 0.f;
        for (int i=0;i<16;i++){ e[i]=expf(pp[i]-mx); s+=e[i]; }
        for (int i=0;i<16;i++) g_probs[tid*16+i] = e[i]/s;
    }
}

// ---------------- K1: per-candidate max|tanh(w)| ---------------------------
__global__ void k_maxes(const float* __restrict__ w1, const float* __restrict__ w2,
                        const float* __restrict__ w3) {
    int cand = blockIdx.x;
    const float* w; int sz;
    if (cand < 16)      { w = w1 + cand*(P*CIN);       sz = P*CIN;  }
    else if (cand < 32) { w = w2 + (cand-16)*(P*9);    sz = P*9;    }
    else                { w = w3 + (cand-32)*(COUT*P); sz = COUT*P; }
    float mx = 0.f;
    for (int i = threadIdx.x; i < sz; i += blockDim.x)
        mx = fmaxf(mx, fabsf(tanhf(w[i])));
    __shared__ float sm[8];
    #pragma unroll
    for (int o=16;o;o>>=1) mx = fmaxf(mx, __shfl_xor_sync(0xffffffffu, mx, o));
    if ((threadIdx.x & 31) == 0) sm[threadIdx.x>>5] = mx;
    __syncthreads();
    if (threadIdx.x < 8) {
        mx = sm[threadIdx.x];
        #pragma unroll
        for (int o=4;o;o>>=1) mx = fmaxf(mx, __shfl_xor_sync(0xffu, mx, o));
        if (threadIdx.x == 0) g_maxes[cand] = mx;
    }
}

// ---------------- K2: build effective weights (3-term bf16 split, raw) ------
__device__ __forceinline__ float quantw(float w, float n, float mx) {
    float t  = tanhf(w);
    float tn = t / (2.0f*mx) + 0.5f;
    float q  = quant_round(tn, n) / n;
    return 2.0f*q - 1.0f;
}

__global__ void k_weights(const float* __restrict__ w1, const float* __restrict__ w2,
                          const float* __restrict__ w3) {
    const float NQ[4] = {3.f, 7.f, 15.f, 31.f};
    int idx = blockIdx.x*blockDim.x + threadIdx.x;
    const int R1 = 4*P*CIN;      // 24576
    const int R2 = 4*P*9;        // 6912
    const int R3 = 4*COUT*P;     // 24576
    if (idx < R1) {
        int j = idx/(P*CIN); int r = idx%(P*CIN); int p=r/CIN; int c=r%CIN;
        float acc = 0.f;
        #pragma unroll
        for (int i=0;i<4;i++){
            int cand = 4*i+j;
            acc += g_probs[cand]*quantw(w1[cand*(P*CIN)+p*CIN+c], NQ[i], g_maxes[cand]);
        }
        float val = acc / NQ[j];                 // fold activation 1/n_j
        float hi  = bf16f(val);
        float mid = bf16f(val - hi);
        float lo  = (val - hi) - mid;            // exact fp32 residual
        int K = c*4 + j;                          // k index 0..127
        uint32_t sw = swz((uint32_t)K*2, (uint32_t)p);
        *(unsigned short*)(g_W1img + (size_t)p*256 + sw)          = bf16u(hi);
        *(unsigned short*)(g_W1img + 49152 + (size_t)p*256 + sw)  = bf16u(mid);
        *(unsigned short*)(g_W1img + 98304 + (size_t)p*256 + sw)  = bf16u(lo);
    } else if (idx < R1+R2) {
        int t = idx-R1; int j=t/(P*9); int r=t%(P*9); int p=r/9; int e=r%9;
        float acc = 0.f;
        #pragma unroll
        for (int i=0;i<4;i++){
            int cand = 4*i+j;
            acc += g_probs[16+cand]*quantw(w2[cand*(P*9)+p*9+e], NQ[i], g_maxes[16+cand]);
        }
        g_W2[(j*P+p)*9 + e] = acc / NQ[j];
    } else if (idx < R1+R2+R3) {
        int t = idx-R1-R2; int j=t/(COUT*P); int r=t%(COUT*P); int o=r/P; int p=r%P;
        float acc = 0.f;
        #pragma unroll
        for (int i=0;i<4;i++){
            int cand = 4*i+j;
            acc += g_probs[32+cand]*quantw(w3[cand*(COUT*P)+o*P+p], NQ[i], g_maxes[32+cand]);
        }
        float val = acc / NQ[j];
        float hi  = bf16f(val);
        float mid = bf16f(val - hi);
        float lo  = (val - hi) - mid;
        int K = p*4 + j;                 // 0..767
        int kc = K >> 7, kl = K & 127;
        uint32_t sw = swz((uint32_t)kl*2, (uint32_t)o);
        size_t base = (size_t)kc*24576 + (size_t)o*256 + sw;
        *(unsigned short*)(g_W3img + base)         = bf16u(hi);
        *(unsigned short*)(g_W3img + base + 8192)  = bf16u(mid);
        *(unsigned short*)(g_W3img + base + 16384) = bf16u(lo);
    }
}

// ---------------- K3: GEMM1, 256 threads, m=32 tiles, pass-outer 3-pass -----
// CTA: D[128 pix, 192 ch] = Aq[128,128] x W1[192,128]^T
// 8 warps: mg=wid&3 -> m0=mg*32; ng=wid>>2 -> 12 n-tiles of 24.
// Per kt: load A frags once; pass-outer order separates acc RAW by ~24 MMAs.
// smem 180224 B: A [0,32K) | Whi [32K,80K) | Wmid [80K,128K) | Wlo [128K,176K)
// epilogue stage [192][132] fp32 reuses arena from 0 after mma.
__global__ __launch_bounds__(256, 1) void k_gemm1(const float* __restrict__ x) {
    extern __shared__ __align__(1024) char smem[];
    const uint32_t sb = smem_u32(smem);
    const int tid = threadIdx.x;
    const int wid = tid >> 5, lid = tid & 31;
    const int n0 = blockIdx.x * 128;
    const int b  = n0 >> 10;
    const int s0 = n0 & 1023;
    const uint32_t W_OFF = 32768;

    // ---- build quantized A tile: rows = pix (256B), k = c*4+j ----
    {
        int c  = tid >> 3;               // input channel 0..31
        int pg = (tid & 7) * 16;         // 16 pixels per thread
        const float* xp = x + ((size_t)(b*CIN + c))*HW + s0 + pg;
        uint32_t bofs = (uint32_t)c * 8;
        #pragma unroll
        for (int u=0; u<4; u++) {
            float4 v4 = *(const float4*)(xp + u*4);
            float vv[4] = {v4.x, v4.y, v4.z, v4.w};
            #pragma unroll
            for (int e=0; e<4; e++) {
                uint32_t row = pg + u*4 + e;
                float v = fminf(fmaxf(vv[e], 0.f), 1.f);
                ushort4 q;
                q.x = bf16u(quant_round(v, 3.f));
                q.y = bf16u(quant_round(v, 7.f));
                q.z = bf16u(quant_round(v, 15.f));
                q.w = bf16u(quant_round(v, 31.f));
                *(ushort4*)(smem + row*256 + swz(bofs, row)) = q;
            }
        }
    }
    // ---- copy pre-swizzled weight images (147456 B) ----
    {
        const float4* src = (const float4*)g_W1img;
        float4* dst = (float4*)(smem + W_OFF);
        #pragma unroll
        for (int it=0; it<36; it++) dst[tid + it*256] = src[tid + it*256];
    }
    __syncthreads();

    // ---- mma mainloop ----
    float acc[96];                        // [sub 2][nt 12][4]
    #pragma unroll
    for (int i=0;i<96;i++) acc[i] = 0.f;

    const int mg = wid & 3, ng = wid >> 2;
    const int m0 = mg * 32;
    const uint32_t swsel = (uint32_t)(lid & 7);
    const uint32_t abase  = sb + (uint32_t)(m0 + (lid & 15)) * 256;
    const uint32_t abase2 = abase + 4096;          // +16 rows
    const int halfa = (lid >> 4) & 1;
    const int halfb = (lid >> 3) & 1;
    const uint32_t bbase = sb + W_OFF + (uint32_t)(lid & 7) * 256;

    #pragma unroll 1
    for (int kt = 0; kt < 8; kt++) {
        uint32_t asw = (((uint32_t)(kt*2 + halfa) ^ swsel) << 4);
        uint32_t ah0,ah1,ah2,ah3, bh0,bh1,bh2,bh3;
        ldm_x4(ah0,ah1,ah2,ah3, abase  + asw);
        ldm_x4(bh0,bh1,bh2,bh3, abase2 + asw);
        uint32_t bsw = (((uint32_t)(kt*2 + halfb) ^ swsel) << 4);
        #pragma unroll
        for (int pass = 0; pass < 3; pass++) {
            uint32_t poff = (uint32_t)pass * 49152u;
            #pragma unroll
            for (int i = 0; i < 12; i++) {
                int nt = ng*12 + i;
                uint32_t w0, w1;
                ldm_x2(w0, w1, bbase + nt*2048 + bsw + poff);
                MMA16816(acc + i*4,      ah0,ah1,ah2,ah3, w0,w1);
                MMA16816(acc + 48 + i*4, bh0,bh1,bh2,bh3, w0,w1);
            }
        }
    }
    __syncthreads();                      // all warps done reading A/W smem

    // ---- epilogue: acc -> stage[ch][132] -> stats + planar STG ----
    float* stage = (float*)smem;          // [192][132]
    {
        int q  = lid & 3;
        int pr = lid >> 2;
        #pragma unroll
        for (int sub = 0; sub < 2; sub++) {
            int col = m0 + sub*16;
            #pragma unroll
            for (int i = 0; i < 12; i++) {
                int ch = (ng*12 + i)*8 + q*2;
                const float* a = acc + sub*48 + i*4;
                stage[(ch  )*132 + col + pr    ] = a[0];
                stage[(ch+1)*132 + col + pr    ] = a[1];
                stage[(ch  )*132 + col + pr + 8] = a[2];
                stage[(ch+1)*132 + col + pr + 8] = a[3];
            }
        }
    }
    __syncthreads();
    if (tid < 192) {
        const float* row = stage + tid*132;
        float s=0.f, q=0.f;
        #pragma unroll 4
        for (int i=0;i<128;i++){ float v=row[i]; s+=v; q=fmaf(v,v,q); }
        atomicAdd(&g_sum1[tid], (double)s);
        atomicAdd(&g_ss1[tid],  (double)q);
    }
    #pragma unroll
    for (int it=0; it<24; it++) {
        int i = tid + it*256;                 // 6144 float4s
        int c = i >> 5, m4 = i & 31;
        float4 v = *(float4*)&stage[c*132 + m4*4];
        *(float4*)&g_out1[(size_t)c*NPIX + n0 + m4*4] = v;
    }
}

// ---------------- K4/K6/K8: BN finalize ------------------------------------
__global__ void k_bnfin(const float* __restrict__ g, const float* __restrict__ bb, int which) {
    int i = threadIdx.x;
    int C = (which==2) ? COUT : P;
    if (i < C) {
        const double* sum = (which==0)?g_sum1:((which==1)?g_sum2:g_sum3);
        const double* ss  = (which==0)?g_ss1 :((which==1)?g_ss2 :g_ss3);
        float* scale = (which==0)?g_scale1:((which==1)?g_scale2:g_scale3);
        float* shift = (which==0)?g_shift1:((which==1)?g_shift2:g_shift3);
        double mean = sum[i] / (double)NPIX;
        double var  = ss[i] / (double)NPIX - mean*mean;
        double sc   = (double)g[i] * rsqrt(var + EPSV);
        scale[i] = (float)sc;
        shift[i] = (float)((double)bb[i] - mean*sc);
    }
}

// ---------------- K5: depthwise 3x3 over 4 j-streams + BN stats ------------
__global__ __launch_bounds__(256) void k_dw() {
    __shared__ float q4[34][36][4];    // j-packed quantized halo
    __shared__ float red[16];
    int blk = blockIdx.x;
    int p = blk >> 8;
    int b = blk & 255;
    int tid = threadIdx.x;
    const float sc = g_scale1[p], sh = g_shift1[p];
    const float* plane = g_out1 + (size_t)p*NPIX + b*HW;
    const float NQ[4] = {3.f,7.f,15.f,31.f};

    for (int i=tid; i<1156; i+=256) {
        int hy = i/34, hx = i - hy*34;
        int yy = hy-1, xx = hx-1;
        float4 q = make_float4(0.f,0.f,0.f,0.f);
        if (yy>=0 && yy<32 && xx>=0 && xx<32) {
            float v = plane[yy*32+xx];
            v = fmaf(v, sc, sh);
            v = fminf(fmaxf(v, 0.f), 1.f);
            q.x = quant_round(v, NQ[0]);
            q.y = quant_round(v, NQ[1]);
            q.z = quant_round(v, NQ[2]);
            q.w = quant_round(v, NQ[3]);
        }
        *(float4*)&q4[hy][hx][0] = q;
    }
    float w[4][9];
    #pragma unroll
    for (int j=0;j<4;j++)
        #pragma unroll
        for (int e=0;e<9;e++) w[j][e] = g_W2[(j*P+p)*9 + e];
    __syncthreads();

    int oy  = tid >> 3;
    int ox0 = (tid & 7) * 4;
    float accp[4] = {0.f,0.f,0.f,0.f};
    #pragma unroll
    for (int ky=0;ky<3;ky++) {
        float4 v[6];
        #pragma unroll
        for (int xx=0;xx<6;xx++) v[xx] = *(float4*)&q4[oy+ky][ox0+xx][0];
        #pragma unroll
        for (int px=0;px<4;px++)
            #pragma unroll
            for (int kx=0;kx<3;kx++) {
                float4 q = v[px+kx];
                float ww;
                ww = w[0][ky*3+kx]; accp[px] = fmaf(ww, q.x, accp[px]);
                ww = w[1][ky*3+kx]; accp[px] = fmaf(ww, q.y, accp[px]);
                ww = w[2][ky*3+kx]; accp[px] = fmaf(ww, q.z, accp[px]);
                ww = w[3][ky*3+kx]; accp[px] = fmaf(ww, q.w, accp[px]);
            }
    }
    float* outp = g_out2 + (size_t)p*NPIX + b*HW + oy*32 + ox0;
    *(float4*)outp = make_float4(accp[0],accp[1],accp[2],accp[3]);

    float rs = accp[0]+accp[1]+accp[2]+accp[3];
    float rq = fmaf(accp[0],accp[0], fmaf(accp[1],accp[1],
               fmaf(accp[2],accp[2], accp[3]*accp[3])));
    #pragma unroll
    for (int o=16;o;o>>=1){ rs += __shfl_xor_sync(0xffffffffu,rs,o);
                            rq += __shfl_xor_sync(0xffffffffu,rq,o); }
    int warp = tid>>5, lane = tid&31;
    if (lane==0){ red[warp]=rs; red[8+warp]=rq; }
    __syncthreads();
    if (tid==0){
        float s=0.f, q=0.f;
        #pragma unroll
        for (int wv=0;wv<8;wv++){ s+=red[wv]; q+=red[8+wv]; }
        atomicAdd(&g_sum2[p], (double)s);
        atomicAdd(&g_ss2[p],  (double)q);
    }
}

// ---------------- K7: GEMM3, 256 threads, M=256/CTA, pass-outer 3-pass ------
// CTA: D[256 pix, 32 ch] = Aq[256,768] x W3[32,768]^T, K in 6 chunks of 128.
// 8 warps: m0=wid*32; each warp does ALL 4 n-tiles (acc 32 regs).
// smem 212992 B: A [0,64K) | W3 [64K,208K) (6 chunks x 24KB: hi|mid|lo 8K each)
// epilogue stage [32][264] fp32 (33792 B) reuses A region after mma.
__global__ __launch_bounds__(256, 1) void k_gemm3() {
    extern __shared__ __align__(1024) char smem[];
    const uint32_t sb = smem_u32(smem);
    const int tid = threadIdx.x;
    const int wid = tid >> 5, lid = tid & 31;
    const int n0 = blockIdx.x * 256;
    const int b  = n0 >> 10;
    const int s0 = n0 & 1023;
    const uint32_t W_OFF = 65536;

    // copy all W3 images (147456 B)
    {
        const float4* src = (const float4*)g_W3img;
        float4* dst = (float4*)(smem + W_OFF);
        #pragma unroll
        for (int it=0; it<36; it++) dst[tid + it*256] = src[tid + it*256];
    }

    const int cb = tid >> 3;           // local channel within chunk 0..31
    const int pg = (tid & 7) * 32;     // 32 pixels per thread
    const uint32_t bofs = (uint32_t)cb * 8;

    const int m0 = wid * 32;
    const uint32_t swsel = (uint32_t)(lid & 7);
    const uint32_t abase  = sb + (uint32_t)(m0 + (lid & 15)) * 256;
    const uint32_t abase2 = abase + 4096;
    const int halfa = (lid >> 4) & 1;
    const int halfb = (lid >> 3) & 1;
    const uint32_t bbase0 = sb + W_OFF + (uint32_t)(lid & 7) * 256;

    float acc[32];                       // [sub 2][nt 4][4]
    #pragma unroll
    for (int i=0;i<32;i++) acc[i] = 0.f;

    #pragma unroll 1
    for (int kc=0; kc<6; kc++) {
        __syncthreads();                 // W copy done / previous chunk mma done
        // build A chunk: BN(scale2) + clip + 4-level quant, bf16-exact ints
        int pch = kc*32 + cb;
        const float* ip = g_out2 + (size_t)pch*NPIX + b*HW + s0 + pg;
        float scl = g_scale2[pch], shf = g_shift2[pch];
        #pragma unroll
        for (int u=0; u<8; u++) {
            float4 v4 = *(const float4*)(ip + u*4);
            float vv[4] = {v4.x, v4.y, v4.z, v4.w};
            #pragma unroll
            for (int e=0; e<4; e++) {
                uint32_t row = pg + u*4 + e;
                float v = fmaf(vv[e], scl, shf);
                v = fminf(fmaxf(v, 0.f), 1.f);
                ushort4 q;
                q.x = bf16u(quant_round(v, 3.f));
                q.y = bf16u(quant_round(v, 7.f));
                q.z = bf16u(quant_round(v, 15.f));
                q.w = bf16u(quant_round(v, 31.f));
                *(ushort4*)(smem + row*256 + swz(bofs, row)) = q;
            }
        }
        __syncthreads();

        const uint32_t bbase = bbase0 + (uint32_t)kc*24576;
        #pragma unroll 1
        for (int kt = 0; kt < 8; kt++) {
            uint32_t asw = (((uint32_t)(kt*2 + halfa) ^ swsel) << 4);
            uint32_t ah0,ah1,ah2,ah3, bh0,bh1,bh2,bh3;
            ldm_x4(ah0,ah1,ah2,ah3, abase  + asw);
            ldm_x4(bh0,bh1,bh2,bh3, abase2 + asw);
            uint32_t bsw = (((uint32_t)(kt*2 + halfb) ^ swsel) << 4);
            #pragma unroll
            for (int pass = 0; pass < 3; pass++) {
                uint32_t poff = (uint32_t)pass * 8192u;
                #pragma unroll
                for (int nt = 0; nt < 4; nt++) {
                    uint32_t w0, w1;
                    ldm_x2(w0, w1, bbase + nt*2048 + bsw + poff);
                    MMA16816(acc + nt*4,      ah0,ah1,ah2,ah3, w0,w1);
                    MMA16816(acc + 16 + nt*4, bh0,bh1,bh2,bh3, w0,w1);
                }
            }
        }
    }
    __syncthreads();

    // epilogue: acc -> stage[32][264] -> stats + planar STG
    float* stage = (float*)smem;
    {
        int q  = lid & 3;
        int pr = lid >> 2;
        #pragma unroll
        for (int sub = 0; sub < 2; sub++) {
            int col = m0 + sub*16;
            #pragma unroll
            for (int nt = 0; nt < 4; nt++) {
                int ch = nt*8 + q*2;
                const float* a = acc + sub*16 + nt*4;
                stage[(ch  )*264 + col + pr    ] = a[0];
                stage[(ch+1)*264 + col + pr    ] = a[1];
                stage[(ch  )*264 + col + pr + 8] = a[2];
                stage[(ch+1)*264 + col + pr + 8] = a[3];
            }
        }
    }
    __syncthreads();
    if (tid < 32) {
        const float* row = stage + tid*264;
        float s=0.f, q=0.f;
        #pragma unroll 4
        for (int i=0;i<256;i++){ float v=row[i]; s+=v; q=fmaf(v,v,q); }
        atomicAdd(&g_sum3[tid], (double)s);
        atomicAdd(&g_ss3[tid],  (double)q);
    }
    #pragma unroll
    for (int it=0; it<8; it++) {
        int i = tid + it*256;               // 2048 float4s
        int ch = i >> 6, m4 = i & 63;
        float4 v = *(float4*)&stage[ch*264 + m4*4];
        *(float4*)&g_out3[(size_t)ch*NPIX + n0 + m4*4] = v;
    }
}

// ---------------- K9: final  out = bn3(out3) + x ---------------------------
__global__ void k_final(const float* __restrict__ x, float* __restrict__ out) {
    int i = blockIdx.x*blockDim.x + threadIdx.x;     // float4 index
    if (i >= (COUT*NPIX)/4) return;
    int s4 = i & 255;
    int o  = (i >> 8) & 31;
    int b  = i >> 13;
    float4 v  = *(const float4*)&g_out3[(size_t)o*NPIX + b*HW + s4*4];
    float4 xi = ((const float4*)x)[i];
    float sc = g_scale3[o], sh = g_shift3[o];
    float4 r;
    r.x = fmaf(v.x, sc, sh) + xi.x;
    r.y = fmaf(v.y, sc, sh) + xi.y;
    r.z = fmaf(v.z, sc, sh) + xi.z;
    r.w = fmaf(v.w, sc, sh) + xi.w;
    ((float4*)out)[i] = r;
}

// ---------------- launch ----------------------------------------------------
extern "C" void kernel_launch(void* const* d_in, const int* in_sizes, int n_in,
                              void* d_out, int out_size) {
    const float* x  = (const float*)d_in[0];
    const float* w1 = (const float*)d_in[1];
    const float* w2 = (const float*)d_in[2];
    const float* w3 = (const float*)d_in[3];
    const float* p1 = (const float*)d_in[4];
    const float* p2 = (const float*)d_in[5];
    const float* p3 = (const float*)d_in[6];
    const float* g1 = (const float*)d_in[7];
    const float* b1 = (const float*)d_in[8];
    const float* g2 = (const float*)d_in[9];
    const float* b2 = (const float*)d_in[10];
    const float* g3 = (const float*)d_in[11];
    const float* b3 = (const float*)d_in[12];
    float* out = (float*)d_out;

    const int SMEM_G1 = 180224;
    const int SMEM_G3 = 212992;
    cudaFuncSetAttribute(k_gemm1, cudaFuncAttributeMaxDynamicSharedMemorySize, SMEM_G1);
    cudaFuncSetAttribute(k_gemm3, cudaFuncAttributeMaxDynamicSharedMemorySize, SMEM_G3);

    k_init<<<1, 256>>>(p1, p2, p3);
    k_maxes<<<48, 256>>>(w1, w2, w3);
    k_weights<<<(4*P*CIN + 4*P*9 + 4*COUT*P + 255)/256, 256>>>(w1, w2, w3);
    k_gemm1<<<NPIX/128, 256, SMEM_G1>>>(x);
    k_bnfin<<<1, 256>>>(g1, b1, 0);
    k_dw<<<P*BATCH, 256>>>();
    k_bnfin<<<1, 256>>>(g2, b2, 1);
    k_gemm3<<<NPIX/256, 256, SMEM_G3>>>();
    k_bnfin<<<1, 256>>>(g3, b3, 2);
    k_final<<<(COUT*NPIX/4 + 255)/256, 256>>>(x, out);
}

// round 16
// speedup vs baseline: 1.0173x; 1.0173x over previous
#include <cuda_runtime.h>
#include <cuda_fp16.h>
#include <math.h>
#include <stdint.h>

#define BATCH 256
#define CIN   32
#define HW    1024          // 32x32
#define P     192
#define COUT  32
#define NPIX  (BATCH*HW)    // 262144
#define EPSV  1e-5

// ---------------- scratch (device globals; no allocations allowed) ----------
__device__ float  g_out1[P*NPIX];        // layer1 raw conv output [p][b*1024+s]
__device__ float  g_out2[P*NPIX];        // layer2 raw conv output
__device__ float  g_out3[COUT*NPIX];     // layer3 raw conv output
__device__ unsigned char g_W1img[98304]; // [hi | lo*2^12] fp16, 192ch x 256B rows
__device__ unsigned char g_W3img[98304]; // [kc 0..5][hi | lo*2^12] fp16, 32ch x 256B rows
__device__ float  g_W2[4*P*9];           // eff W2 / n_j, [j][p][9]
__device__ float  g_maxes[48];
__device__ float  g_probs[48];
__device__ double g_sum1[P],  g_ss1[P];
__device__ double g_sum2[P],  g_ss2[P];
__device__ double g_sum3[COUT], g_ss3[COUT];
__device__ float  g_scale1[P], g_shift1[P];
__device__ float  g_scale2[P], g_shift2[P];
__device__ float  g_scale3[COUT], g_shift3[COUT];

__device__ __forceinline__ float quant_round(float v, float n) {
    // match jnp.round(v*n): fp32 multiply (RN), then round-half-even via magic add
    const float MAGIC = 12582912.0f;     // 1.5 * 2^23
    float t = __fmul_rn(v, n);
    return __fsub_rn(__fadd_rn(t, MAGIC), MAGIC);
}

__device__ __forceinline__ unsigned short h16u(float f) {
    __half h = __float2half_rn(f);
    return *reinterpret_cast<unsigned short*>(&h);
}
__device__ __forceinline__ float h16f(float f) {
    return __half2float(__float2half_rn(f));
}

// swizzle within a 256-byte row: XOR the 16B-unit index with (row & 7)
__device__ __forceinline__ uint32_t swz(uint32_t byteInRow, uint32_t row) {
    return ((((byteInRow >> 4) ^ (row & 7u)) << 4) | (byteInRow & 15u));
}

// Exponent-shift packed non-negative fp16 ints by 2^-12 (exact; +0 stays 0).
// m in [1,31]: exp field >= 15 > 12 -> stays normal. fp16 exp at bits [10:15).
__device__ __forceinline__ uint32_t lo12h(uint32_t h) {
    return __vsub2(h, 0x30003000u) & ~__vcmpeq2(h, 0u);
}

// ---------------- mma.sync / ldmatrix helpers (compute_100-legal) -----------
__device__ __forceinline__ uint32_t smem_u32(const void* p) {
    uint32_t a;
    asm("{ .reg .u64 t; cvta.to.shared.u64 t, %1; cvt.u32.u64 %0, t; }" : "=r"(a) : "l"(p));
    return a;
}
__device__ __forceinline__ void ldm_x4(uint32_t& r0, uint32_t& r1, uint32_t& r2, uint32_t& r3,
                                       uint32_t addr) {
    asm volatile("ldmatrix.sync.aligned.m8n8.x4.shared.b16 {%0,%1,%2,%3}, [%4];"
                 : "=r"(r0), "=r"(r1), "=r"(r2), "=r"(r3) : "r"(addr));
}
__device__ __forceinline__ void ldm_x2(uint32_t& r0, uint32_t& r1, uint32_t addr) {
    asm volatile("ldmatrix.sync.aligned.m8n8.x2.shared.b16 {%0,%1}, [%2];"
                 : "=r"(r0), "=r"(r1) : "r"(addr));
}
#define MMA16816(C, a0, a1, a2, a3, b0, b1) \
    asm volatile("mma.sync.aligned.m16n8k16.row.col.f32.f16.f16.f32 " \
                 "{%0,%1,%2,%3}, {%4,%5,%6,%7}, {%8,%9}, {%0,%1,%2,%3};" \
                 : "+f"((C)[0]), "+f"((C)[1]), "+f"((C)[2]), "+f"((C)[3]) \
                 : "r"(a0), "r"(a1), "r"(a2), "r"(a3), "r"(b0), "r"(b1))

// ---------------- K0: zero stats + softmax --------------------------------
__global__ void k_init(const float* __restrict__ p1, const float* __restrict__ p2,
                       const float* __restrict__ p3) {
    int tid = threadIdx.x;
    if (tid < P)    { g_sum1[tid]=0.0; g_ss1[tid]=0.0; g_sum2[tid]=0.0; g_ss2[tid]=0.0; }
    if (tid < COUT) { g_sum3[tid]=0.0; g_ss3[tid]=0.0; }
    if (tid < 3) {
        const float* pp = (tid==0) ? p1 : ((tid==1) ? p2 : p3);
        float mx = -1e30f;
        for (int i=0;i<16;i++) mx = fmaxf(mx, pp[i]);
        float e[16]; float s = 0.f;
        for (int i=0;i<16;i++){ e[i]=expf(pp[i]-mx); s+=e[i]; }
        for (int i=0;i<16;i++) g_probs[tid*16+i] = e[i]/s;
    }
}

// ---------------- K1: per-candidate max|tanh(w)| ---------------------------
__global__ void k_maxes(const float* __restrict__ w1, const float* __restrict__ w2,
                        const float* __restrict__ w3) {
    int cand = blockIdx.x;
    const float* w; int sz;
    if (cand < 16)      { w = w1 + cand*(P*CIN);       sz = P*CIN;  }
    else if (cand < 32) { w = w2 + (cand-16)*(P*9);    sz = P*9;    }
    else                { w = w3 + (cand-32)*(COUT*P); sz = COUT*P; }
    float mx = 0.f;
    for (int i = threadIdx.x; i < sz; i += blockDim.x)
        mx = fmaxf(mx, fabsf(tanhf(w[i])));
    __shared__ float sm[8];
    #pragma unroll
    for (int o=16;o;o>>=1) mx = fmaxf(mx, __shfl_xor_sync(0xffffffffu, mx, o));
    if ((threadIdx.x & 31) == 0) sm[threadIdx.x>>5] = mx;
    __syncthreads();
    if (threadIdx.x < 8) {
        mx = sm[threadIdx.x];
        #pragma unroll
        for (int o=4;o;o>>=1) mx = fmaxf(mx, __shfl_xor_sync(0xffu, mx, o));
        if (threadIdx.x == 0) g_maxes[cand] = mx;
    }
}

// ---------------- K2: build effective weights (fp16 hi + lo*2^12) -----------
// w = hi + (lo*2^12)*2^-12; lo*2^12 is fp16-NORMAL (avoids the subnormal
// flush that killed the raw-residual variant). A-side partner m*2^-12 is an
// exact exponent shift in registers. Total representation error ~2^-24|w|.
__device__ __forceinline__ float quantw(float w, float n, float mx) {
    float t  = tanhf(w);
    float tn = t / (2.0f*mx) + 0.5f;
    float q  = quant_round(tn, n) / n;
    return 2.0f*q - 1.0f;
}

__global__ void k_weights(const float* __restrict__ w1, const float* __restrict__ w2,
                          const float* __restrict__ w3) {
    const float NQ[4] = {3.f, 7.f, 15.f, 31.f};
    int idx = blockIdx.x*blockDim.x + threadIdx.x;
    const int R1 = 4*P*CIN;      // 24576
    const int R2 = 4*P*9;        // 6912
    const int R3 = 4*COUT*P;     // 24576
    if (idx < R1) {
        int j = idx/(P*CIN); int r = idx%(P*CIN); int p=r/CIN; int c=r%CIN;
        float acc = 0.f;
        #pragma unroll
        for (int i=0;i<4;i++){
            int cand = 4*i+j;
            acc += g_probs[cand]*quantw(w1[cand*(P*CIN)+p*CIN+c], NQ[i], g_maxes[cand]);
        }
        float val = acc / NQ[j];                 // fold activation 1/n_j
        float hi  = h16f(val);
        float lo  = (val - hi) * 4096.0f;        // exact *2^12 in fp32
        int K = c*4 + j;                          // k index 0..127
        uint32_t sw = swz((uint32_t)K*2, (uint32_t)p);
        *(unsigned short*)(g_W1img + (size_t)p*256 + sw)          = h16u(hi);
        *(unsigned short*)(g_W1img + 49152 + (size_t)p*256 + sw)  = h16u(lo);
    } else if (idx < R1+R2) {
        int t = idx-R1; int j=t/(P*9); int r=t%(P*9); int p=r/9; int e=r%9;
        float acc = 0.f;
        #pragma unroll
        for (int i=0;i<4;i++){
            int cand = 4*i+j;
            acc += g_probs[16+cand]*quantw(w2[cand*(P*9)+p*9+e], NQ[i], g_maxes[16+cand]);
        }
        g_W2[(j*P+p)*9 + e] = acc / NQ[j];
    } else if (idx < R1+R2+R3) {
        int t = idx-R1-R2; int j=t/(COUT*P); int r=t%(COUT*P); int o=r/P; int p=r%P;
        float acc = 0.f;
        #pragma unroll
        for (int i=0;i<4;i++){
            int cand = 4*i+j;
            acc += g_probs[32+cand]*quantw(w3[cand*(COUT*P)+o*P+p], NQ[i], g_maxes[32+cand]);
        }
        float val = acc / NQ[j];
        float hi  = h16f(val);
        float lo  = (val - hi) * 4096.0f;
        int K = p*4 + j;                 // 0..767
        int kc = K >> 7, kl = K & 127;
        uint32_t sw = swz((uint32_t)kl*2, (uint32_t)o);
        size_t base = (size_t)kc*16384 + (size_t)o*256 + sw;
        *(unsigned short*)(g_W3img + base)        = h16u(hi);
        *(unsigned short*)(g_W3img + base + 8192) = h16u(lo);
    }
}

// ---------------- K3: GEMM1, 256 threads, m=32 tiles, 2-pass fp16 -----------
// CTA: D[128 pix, 192 ch] = Aq[128,128] x W1[192,128]^T
// hi pass: m x hi;  lo pass: (m*2^-12, regs) x (lo*2^12).
// 8 warps: mg=wid&3 -> m0=mg*32; ng=wid>>2 -> 12 n-tiles of 24.
// smem 131072 B: A [0,32K) | Whi [32K,80K) | Wlo [80K,128K)
// epilogue stage [192][132] fp32 (101376 B) reuses arena from 0 after mma.
__global__ __launch_bounds__(256, 1) void k_gemm1(const float* __restrict__ x) {
    extern __shared__ __align__(1024) char smem[];
    const uint32_t sb = smem_u32(smem);
    const int tid = threadIdx.x;
    const int wid = tid >> 5, lid = tid & 31;
    const int n0 = blockIdx.x * 128;
    const int b  = n0 >> 10;
    const int s0 = n0 & 1023;
    const uint32_t W_OFF = 32768;

    // ---- build quantized A tile: rows = pix (256B), k = c*4+j ----
    {
        int c  = tid >> 3;               // input channel 0..31
        int pg = (tid & 7) * 16;         // 16 pixels per thread
        const float* xp = x + ((size_t)(b*CIN + c))*HW + s0 + pg;
        uint32_t bofs = (uint32_t)c * 8;
        #pragma unroll
        for (int u=0; u<4; u++) {
            float4 v4 = *(const float4*)(xp + u*4);
            float vv[4] = {v4.x, v4.y, v4.z, v4.w};
            #pragma unroll
            for (int e=0; e<4; e++) {
                uint32_t row = pg + u*4 + e;
                float v = fminf(fmaxf(vv[e], 0.f), 1.f);
                ushort4 q;
                q.x = h16u(quant_round(v, 3.f));
                q.y = h16u(quant_round(v, 7.f));
                q.z = h16u(quant_round(v, 15.f));
                q.w = h16u(quant_round(v, 31.f));
                *(ushort4*)(smem + row*256 + swz(bofs, row)) = q;
            }
        }
    }
    // ---- copy pre-swizzled weight images (98304 B) ----
    {
        const float4* src = (const float4*)g_W1img;
        float4* dst = (float4*)(smem + W_OFF);
        #pragma unroll
        for (int it=0; it<24; it++) dst[tid + it*256] = src[tid + it*256];
    }
    __syncthreads();

    // ---- mma mainloop ----
    float acc[96];                        // [sub 2][nt 12][4]
    #pragma unroll
    for (int i=0;i<96;i++) acc[i] = 0.f;

    const int mg = wid & 3, ng = wid >> 2;
    const int m0 = mg * 32;
    const uint32_t swsel = (uint32_t)(lid & 7);
    const uint32_t abase  = sb + (uint32_t)(m0 + (lid & 15)) * 256;
    const uint32_t abase2 = abase + 4096;          // +16 rows
    const int halfa = (lid >> 4) & 1;
    const int halfb = (lid >> 3) & 1;
    const uint32_t bbase = sb + W_OFF + (uint32_t)(lid & 7) * 256;

    #pragma unroll 1
    for (int kt = 0; kt < 8; kt++) {
        uint32_t asw = (((uint32_t)(kt*2 + halfa) ^ swsel) << 4);
        uint32_t ah0,ah1,ah2,ah3, bh0,bh1,bh2,bh3;
        ldm_x4(ah0,ah1,ah2,ah3, abase  + asw);
        ldm_x4(bh0,bh1,bh2,bh3, abase2 + asw);
        uint32_t al0 = lo12h(ah0), al1 = lo12h(ah1), al2 = lo12h(ah2), al3 = lo12h(ah3);
        uint32_t bl0 = lo12h(bh0), bl1 = lo12h(bh1), bl2 = lo12h(bh2), bl3 = lo12h(bh3);
        uint32_t bsw = (((uint32_t)(kt*2 + halfb) ^ swsel) << 4);
        #pragma unroll
        for (int i = 0; i < 12; i++) {
            int nt = ng*12 + i;
            uint32_t w0, w1;
            ldm_x2(w0, w1, bbase + nt*2048 + bsw);
            MMA16816(acc + i*4,      ah0,ah1,ah2,ah3, w0,w1);
            MMA16816(acc + 48 + i*4, bh0,bh1,bh2,bh3, w0,w1);
            ldm_x2(w0, w1, bbase + nt*2048 + bsw + 49152);
            MMA16816(acc + i*4,      al0,al1,al2,al3, w0,w1);
            MMA16816(acc + 48 + i*4, bl0,bl1,bl2,bl3, w0,w1);
        }
    }
    __syncthreads();                      // all warps done reading A/W smem

    // ---- epilogue: acc -> stage[ch][132] -> stats + planar STG ----
    float* stage = (float*)smem;          // [192][132]
    {
        int q  = lid & 3;
        int pr = lid >> 2;
        #pragma unroll
        for (int sub = 0; sub < 2; sub++) {
            int col = m0 + sub*16;
            #pragma unroll
            for (int i = 0; i < 12; i++) {
                int ch = (ng*12 + i)*8 + q*2;
                const float* a = acc + sub*48 + i*4;
                stage[(ch  )*132 + col + pr    ] = a[0];
                stage[(ch+1)*132 + col + pr    ] = a[1];
                stage[(ch  )*132 + col + pr + 8] = a[2];
                stage[(ch+1)*132 + col + pr + 8] = a[3];
            }
        }
    }
    __syncthreads();
    if (tid < 192) {
        const float* row = stage + tid*132;
        float s=0.f, q=0.f;
        #pragma unroll 4
        for (int i=0;i<128;i++){ float v=row[i]; s+=v; q=fmaf(v,v,q); }
        atomicAdd(&g_sum1[tid], (double)s);
        atomicAdd(&g_ss1[tid],  (double)q);
    }
    #pragma unroll
    for (int it=0; it<24; it++) {
        int i = tid + it*256;                 // 6144 float4s
        int c = i >> 5, m4 = i & 31;
        float4 v = *(float4*)&stage[c*132 + m4*4];
        *(float4*)&g_out1[(size_t)c*NPIX + n0 + m4*4] = v;
    }
}

// ---------------- K4/K6/K8: BN finalize ------------------------------------
__global__ void k_bnfin(const float* __restrict__ g, const float* __restrict__ bb, int which) {
    int i = threadIdx.x;
    int C = (which==2) ? COUT : P;
    if (i < C) {
        const double* sum = (which==0)?g_sum1:((which==1)?g_sum2:g_sum3);
        const double* ss  = (which==0)?g_ss1 :((which==1)?g_ss2 :g_ss3);
        float* scale = (which==0)?g_scale1:((which==1)?g_scale2:g_scale3);
        float* shift = (which==0)?g_shift1:((which==1)?g_shift2:g_shift3);
        double mean = sum[i] / (double)NPIX;
        double var  = ss[i] / (double)NPIX - mean*mean;
        double sc   = (double)g[i] * rsqrt(var + EPSV);
        scale[i] = (float)sc;
        shift[i] = (float)((double)bb[i] - mean*sc);
    }
}

// ---------------- K5: depthwise 3x3 over 4 j-streams + BN stats ------------
__global__ __launch_bounds__(256) void k_dw() {
    __shared__ float q4[34][36][4];    // j-packed quantized halo
    __shared__ float red[16];
    int blk = blockIdx.x;
    int p = blk >> 8;
    int b = blk & 255;
    int tid = threadIdx.x;
    const float sc = g_scale1[p], sh = g_shift1[p];
    const float* plane = g_out1 + (size_t)p*NPIX + b*HW;
    const float NQ[4] = {3.f,7.f,15.f,31.f};

    for (int i=tid; i<1156; i+=256) {
        int hy = i/34, hx = i - hy*34;
        int yy = hy-1, xx = hx-1;
        float4 q = make_float4(0.f,0.f,0.f,0.f);
        if (yy>=0 && yy<32 && xx>=0 && xx<32) {
            float v = plane[yy*32+xx];
            v = fmaf(v, sc, sh);
            v = fminf(fmaxf(v, 0.f), 1.f);
            q.x = quant_round(v, NQ[0]);
            q.y = quant_round(v, NQ[1]);
            q.z = quant_round(v, NQ[2]);
            q.w = quant_round(v, NQ[3]);
        }
        *(float4*)&q4[hy][hx][0] = q;
    }
    float w[4][9];
    #pragma unroll
    for (int j=0;j<4;j++)
        #pragma unroll
        for (int e=0;e<9;e++) w[j][e] = g_W2[(j*P+p)*9 + e];
    __syncthreads();

    int oy  = tid >> 3;
    int ox0 = (tid & 7) * 4;
    float accp[4] = {0.f,0.f,0.f,0.f};
    #pragma unroll
    for (int ky=0;ky<3;ky++) {
        float4 v[6];
        #pragma unroll
        for (int xx=0;xx<6;xx++) v[xx] = *(float4*)&q4[oy+ky][ox0+xx][0];
        #pragma unroll
        for (int px=0;px<4;px++)
            #pragma unroll
            for (int kx=0;kx<3;kx++) {
                float4 q = v[px+kx];
                float ww;
                ww = w[0][ky*3+kx]; accp[px] = fmaf(ww, q.x, accp[px]);
                ww = w[1][ky*3+kx]; accp[px] = fmaf(ww, q.y, accp[px]);
                ww = w[2][ky*3+kx]; accp[px] = fmaf(ww, q.z, accp[px]);
                ww = w[3][ky*3+kx]; accp[px] = fmaf(ww, q.w, accp[px]);
            }
    }
    float* outp = g_out2 + (size_t)p*NPIX + b*HW + oy*32 + ox0;
    *(float4*)outp = make_float4(accp[0],accp[1],accp[2],accp[3]);

    float rs = accp[0]+accp[1]+accp[2]+accp[3];
    float rq = fmaf(accp[0],accp[0], fmaf(accp[1],accp[1],
               fmaf(accp[2],accp[2], accp[3]*accp[3])));
    #pragma unroll
    for (int o=16;o;o>>=1){ rs += __shfl_xor_sync(0xffffffffu,rs,o);
                            rq += __shfl_xor_sync(0xffffffffu,rq,o); }
    int warp = tid>>5, lane = tid&31;
    if (lane==0){ red[warp]=rs; red[8+warp]=rq; }
    __syncthreads();
    if (tid==0){
        float s=0.f, q=0.f;
        #pragma unroll
        for (int wv=0;wv<8;wv++){ s+=red[wv]; q+=red[8+wv]; }
        atomicAdd(&g_sum2[p], (double)s);
        atomicAdd(&g_ss2[p],  (double)q);
    }
}

// ---------------- K7: GEMM3, 256 threads, m=32 tiles, 2-pass fp16 -----------
// CTA: D[128 pix, 32 ch] = Aq[128,768] x W3[32,768]^T, K in 6 chunks of 128.
// 8 warps: mg=wid&3 -> m0=mg*32; ng=wid>>2 -> 2 n-tiles of 4.
// smem 131072 B: A [0,32K) | W3 [32K,128K) (6 chunks x 16KB: hi|lo 8K each)
// epilogue stage [32][132] fp32 reuses arena from 0.
__global__ __launch_bounds__(256, 1) void k_gemm3() {
    extern __shared__ __align__(1024) char smem[];
    const uint32_t sb = smem_u32(smem);
    const int tid = threadIdx.x;
    const int wid = tid >> 5, lid = tid & 31;
    const int n0 = blockIdx.x * 128;
    const int b  = n0 >> 10;
    const int s0 = n0 & 1023;
    const uint32_t W_OFF = 32768;

    // copy all W3 images (98304 B)
    {
        const float4* src = (const float4*)g_W3img;
        float4* dst = (float4*)(smem + W_OFF);
        #pragma unroll
        for (int it=0; it<24; it++) dst[tid + it*256] = src[tid + it*256];
    }

    const int cb = tid >> 3;           // local channel within chunk 0..31
    const int pg = (tid & 7) * 16;
    const uint32_t bofs = (uint32_t)cb * 8;

    const int mg = wid & 3, ng = wid >> 2;
    const int m0 = mg * 32;
    const uint32_t swsel = (uint32_t)(lid & 7);
    const uint32_t abase  = sb + (uint32_t)(m0 + (lid & 15)) * 256;
    const uint32_t abase2 = abase + 4096;
    const int halfa = (lid >> 4) & 1;
    const int halfb = (lid >> 3) & 1;
    const uint32_t bbase0 = sb + W_OFF + (uint32_t)(lid & 7) * 256;

    float acc[16];                       // [sub 2][nt 2][4]
    #pragma unroll
    for (int i=0;i<16;i++) acc[i] = 0.f;

    #pragma unroll 1
    for (int kc=0; kc<6; kc++) {
        __syncthreads();                 // W copy done / previous chunk mma done
        // build A chunk: BN(scale2) + clip + 4-level quant (f16-exact ints)
        int pch = kc*32 + cb;
        const float* ip = g_out2 + (size_t)pch*NPIX + b*HW + s0 + pg;
        float scl = g_scale2[pch], shf = g_shift2[pch];
        #pragma unroll
        for (int u=0; u<4; u++) {
            float4 v4 = *(const float4*)(ip + u*4);
            float vv[4] = {v4.x, v4.y, v4.z, v4.w};
            #pragma unroll
            for (int e=0; e<4; e++) {
                uint32_t row = pg + u*4 + e;
                float v = fmaf(vv[e], scl, shf);
                v = fminf(fmaxf(v, 0.f), 1.f);
                ushort4 q;
                q.x = h16u(quant_round(v, 3.f));
                q.y = h16u(quant_round(v, 7.f));
                q.z = h16u(quant_round(v, 15.f));
                q.w = h16u(quant_round(v, 31.f));
                *(ushort4*)(smem + row*256 + swz(bofs, row)) = q;
            }
        }
        __syncthreads();

        const uint32_t bbase = bbase0 + (uint32_t)kc*16384;
        #pragma unroll 1
        for (int kt = 0; kt < 8; kt++) {
            uint32_t asw = (((uint32_t)(kt*2 + halfa) ^ swsel) << 4);
            uint32_t ah0,ah1,ah2,ah3, bh0,bh1,bh2,bh3;
            ldm_x4(ah0,ah1,ah2,ah3, abase  + asw);
            ldm_x4(bh0,bh1,bh2,bh3, abase2 + asw);
            uint32_t al0 = lo12h(ah0), al1 = lo12h(ah1), al2 = lo12h(ah2), al3 = lo12h(ah3);
            uint32_t bl0 = lo12h(bh0), bl1 = lo12h(bh1), bl2 = lo12h(bh2), bl3 = lo12h(bh3);
            uint32_t bsw = (((uint32_t)(kt*2 + halfb) ^ swsel) << 4);
            #pragma unroll
            for (int i = 0; i < 2; i++) {
                int nt = ng*2 + i;
                uint32_t w0, w1;
                ldm_x2(w0, w1, bbase + nt*2048 + bsw);
                MMA16816(acc + i*4,     ah0,ah1,ah2,ah3, w0,w1);
                MMA16816(acc + 8 + i*4, bh0,bh1,bh2,bh3, w0,w1);
                ldm_x2(w0, w1, bbase + nt*2048 + bsw + 8192);
                MMA16816(acc + i*4,     al0,al1,al2,al3, w0,w1);
                MMA16816(acc + 8 + i*4, bl0,bl1,bl2,bl3, w0,w1);
            }
        }
    }
    __syncthreads();

    // epilogue: acc -> stage[32][132] -> stats + planar STG
    float* stage = (float*)smem;
    {
        int q  = lid & 3;
        int pr = lid >> 2;
        #pragma unroll
        for (int sub = 0; sub < 2; sub++) {
            int col = m0 + sub*16;
            #pragma unroll
            for (int i = 0; i < 2; i++) {
                int ch = (ng*2 + i)*8 + q*2;
                const float* a = acc + sub*8 + i*4;
                stage[(ch  )*132 + col + pr    ] = a[0];
                stage[(ch+1)*132 + col + pr    ] = a[1];
                stage[(ch  )*132 + col + pr + 8] = a[2];
                stage[(ch+1)*132 + col + pr + 8] = a[3];
            }
        }
    }
    __syncthreads();
    if (tid < 32) {
        const float* row = stage + tid*132;
        float s=0.f, q=0.f;
        #pragma unroll 4
        for (int i=0;i<128;i++){ float v=row[i]; s+=v; q=fmaf(v,v,q); }
        atomicAdd(&g_sum3[tid], (double)s);
        atomicAdd(&g_ss3[tid],  (double)q);
    }
    #pragma unroll
    for (int it=0; it<4; it++) {
        int i = tid + it*256;               // 1024 float4s
        int ch = i >> 5, m4 = i & 31;
        float4 v = *(float4*)&stage[ch*132 + m4*4];
        *(float4*)&g_out3[(size_t)ch*NPIX + n0 + m4*4] = v;
    }
}

// ---------------- K9: final  out = bn3(out3) + x ---------------------------
__global__ void k_final(const float* __restrict__ x, float* __restrict__ out) {
    int i = blockIdx.x*blockDim.x + threadIdx.x;     // float4 index
    if (i >= (COUT*NPIX)/4) return;
    int s4 = i & 255;
    int o  = (i >> 8) & 31;
    int b  = i >> 13;
    float4 v  = *(const float4*)&g_out3[(size_t)o*NPIX + b*HW + s4*4];
    float4 xi = ((const float4*)x)[i];
    float sc = g_scale3[o], sh = g_shift3[o];
    float4 r;
    r.x = fmaf(v.x, sc, sh) + xi.x;
    r.y = fmaf(v.y, sc, sh) + xi.y;
    r.z = fmaf(v.z, sc, sh) + xi.z;
    r.w = fmaf(v.w, sc, sh) + xi.w;
    ((float4*)out)[i] = r;
}

// ---------------- launch ----------------------------------------------------
extern "C" void kernel_launch(void* const* d_in, const int* in_sizes, int n_in,
                              void* d_out, int out_size) {
    const float* x  = (const float*)d_in[0];
    const float* w1 = (const float*)d_in[1];
    const float* w2 = (const float*)d_in[2];
    const float* w3 = (const float*)d_in[3];
    const float* p1 = (const float*)d_in[4];
    const float* p2 = (const float*)d_in[5];
    const float* p3 = (const float*)d_in[6];
    const float* g1 = (const float*)d_in[7];
    const float* b1 = (const float*)d_in[8];
    const float* g2 = (const float*)d_in[9];
    const float* b2 = (const float*)d_in[10];
    const float* g3 = (const float*)d_in[11];
    const float* b3 = (const float*)d_in[12];
    float* out = (float*)d_out;

    const int SMEM_GEMM = 131072;
    cudaFuncSetAttribute(k_gemm1, cudaFuncAttributeMaxDynamicSharedMemorySize, SMEM_GEMM);
    cudaFuncSetAttribute(k_gemm3, cudaFuncAttributeMaxDynamicSharedMemorySize, SMEM_GEMM);

    k_init<<<1, 256>>>(p1, p2, p3);
    k_maxes<<<48, 256>>>(w1, w2, w3);
    k_weights<<<(4*P*CIN + 4*P*9 + 4*COUT*P + 255)/256, 256>>>(w1, w2, w3);
    k_gemm1<<<NPIX/128, 256, SMEM_GEMM>>>(x);
    k_bnfin<<<1, 256>>>(g1, b1, 0);
    k_dw<<<P*BATCH, 256>>>();
    k_bnfin<<<1, 256>>>(g2, b2, 1);
    k_gemm3<<<NPIX/128, 256, SMEM_GEMM>>>();
    k_bnfin<<<1, 256>>>(g3, b3, 2);
    k_final<<<(COUT*NPIX/4 + 255)/256, 256>>>(x, out);
}

// round 17
// speedup vs baseline: 1.1374x; 1.1180x over previous
#include <cuda_runtime.h>
#include <cuda_fp16.h>
#include <math.h>
#include <stdint.h>

#define BATCH 256
#define CIN   32
#define HW    1024          // 32x32
#define P     192
#define COUT  32
#define NPIX  (BATCH*HW)    // 262144
#define EPSV  1e-5

// ---------------- scratch (device globals; no allocations allowed) ----------
__device__ float  g_out1[P*NPIX];        // layer1 raw conv output [p][b*1024+s]
__device__ float  g_out2[P*NPIX];        // layer2 raw conv output
__device__ float  g_out3[COUT*NPIX];     // layer3 raw conv output
__device__ unsigned char g_W1img[98304]; // [hi | lo*2^12] fp16, 192ch x 256B rows
__device__ unsigned char g_W3img[98304]; // [kc 0..5][hi | lo*2^12] fp16, 32ch x 256B rows
__device__ float  g_W2[4*P*9];           // eff W2 / n_j, [j][p][9]
__device__ float  g_maxes[48];
__device__ float  g_probs[48];
__device__ double g_sum1[P],  g_ss1[P];
__device__ double g_sum2[P],  g_ss2[P];
__device__ double g_sum3[COUT], g_ss3[COUT];
__device__ float  g_scale1[P], g_shift1[P];
__device__ float  g_scale2[P], g_shift2[P];
__device__ float  g_scale3[COUT], g_shift3[COUT];

__device__ __forceinline__ float quant_round(float v, float n) {
    // match jnp.round(v*n): fp32 multiply (RN), then round-half-even via magic add
    const float MAGIC = 12582912.0f;     // 1.5 * 2^23
    float t = __fmul_rn(v, n);
    return __fsub_rn(__fadd_rn(t, MAGIC), MAGIC);
}

__device__ __forceinline__ unsigned short h16u(float f) {
    __half h = __float2half_rn(f);
    return *reinterpret_cast<unsigned short*>(&h);
}
__device__ __forceinline__ float h16f(float f) {
    return __half2float(__float2half_rn(f));
}

// swizzle within a 256-byte row: XOR the 16B-unit index with (row & 7)
__device__ __forceinline__ uint32_t swz(uint32_t byteInRow, uint32_t row) {
    return ((((byteInRow >> 4) ^ (row & 7u)) << 4) | (byteInRow & 15u));
}

// Exponent-shift packed non-negative fp16 ints by 2^-12 (exact; +0 stays 0).
// m in [1,31]: exp field >= 15 > 12 -> stays normal. fp16 exp at bits [10:15).
__device__ __forceinline__ uint32_t lo12h(uint32_t h) {
    return __vsub2(h, 0x30003000u) & ~__vcmpeq2(h, 0u);
}

// ---------------- mma.sync / ldmatrix helpers (compute_100-legal) -----------
__device__ __forceinline__ uint32_t smem_u32(const void* p) {
    uint32_t a;
    asm("{ .reg .u64 t; cvta.to.shared.u64 t, %1; cvt.u32.u64 %0, t; }" : "=r"(a) : "l"(p));
    return a;
}
__device__ __forceinline__ void ldm_x4(uint32_t& r0, uint32_t& r1, uint32_t& r2, uint32_t& r3,
                                       uint32_t addr) {
    asm volatile("ldmatrix.sync.aligned.m8n8.x4.shared.b16 {%0,%1,%2,%3}, [%4];"
                 : "=r"(r0), "=r"(r1), "=r"(r2), "=r"(r3) : "r"(addr));
}
__device__ __forceinline__ void ldm_x2(uint32_t& r0, uint32_t& r1, uint32_t addr) {
    asm volatile("ldmatrix.sync.aligned.m8n8.x2.shared.b16 {%0,%1}, [%2];"
                 : "=r"(r0), "=r"(r1) : "r"(addr));
}
#define MMA16816(C, a0, a1, a2, a3, b0, b1) \
    asm volatile("mma.sync.aligned.m16n8k16.row.col.f32.f16.f16.f32 " \
                 "{%0,%1,%2,%3}, {%4,%5,%6,%7}, {%8,%9}, {%0,%1,%2,%3};" \
                 : "+f"((C)[0]), "+f"((C)[1]), "+f"((C)[2]), "+f"((C)[3]) \
                 : "r"(a0), "r"(a1), "r"(a2), "r"(a3), "r"(b0), "r"(b1))

// ---------------- K0: zero stats + softmax --------------------------------
__global__ void k_init(const float* __restrict__ p1, const float* __restrict__ p2,
                       const float* __restrict__ p3) {
    int tid = threadIdx.x;
    if (tid < P)    { g_sum1[tid]=0.0; g_ss1[tid]=0.0; g_sum2[tid]=0.0; g_ss2[tid]=0.0; }
    if (tid < COUT) { g_sum3[tid]=0.0; g_ss3[tid]=0.0; }
    if (tid < 3) {
        const float* pp = (tid==0) ? p1 : ((tid==1) ? p2 : p3);
        float mx = -1e30f;
        for (int i=0;i<16;i++) mx = fmaxf(mx, pp[i]);
        float e[16]; float s = 0.f;
        for (int i=0;i<16;i++){ e[i]=expf(pp[i]-mx); s+=e[i]; }
        for (int i=0;i<16;i++) g_probs[tid*16+i] = e[i]/s;
    }
}

// ---------------- K1: per-candidate max|tanh(w)| ---------------------------
__global__ void k_maxes(const float* __restrict__ w1, const float* __restrict__ w2,
                        const float* __restrict__ w3) {
    int cand = blockIdx.x;
    const float* w; int sz;
    if (cand < 16)      { w = w1 + cand*(P*CIN);       sz = P*CIN;  }
    else if (cand < 32) { w = w2 + (cand-16)*(P*9);    sz = P*9;    }
    else                { w = w3 + (cand-32)*(COUT*P); sz = COUT*P; }
    float mx = 0.f;
    for (int i = threadIdx.x; i < sz; i += blockDim.x)
        mx = fmaxf(mx, fabsf(tanhf(w[i])));
    __shared__ float sm[8];
    #pragma unroll
    for (int o=16;o;o>>=1) mx = fmaxf(mx, __shfl_xor_sync(0xffffffffu, mx, o));
    if ((threadIdx.x & 31) == 0) sm[threadIdx.x>>5] = mx;
    __syncthreads();
    if (threadIdx.x < 8) {
        mx = sm[threadIdx.x];
        #pragma unroll
        for (int o=4;o;o>>=1) mx = fmaxf(mx, __shfl_xor_sync(0xffu, mx, o));
        if (threadIdx.x == 0) g_maxes[cand] = mx;
    }
}

// ---------------- K2: build effective weights (fp16 hi + lo*2^12) -----------
__device__ __forceinline__ float quantw(float w, float n, float mx) {
    float t  = tanhf(w);
    float tn = t / (2.0f*mx) + 0.5f;
    float q  = quant_round(tn, n) / n;
    return 2.0f*q - 1.0f;
}

__global__ void k_weights(const float* __restrict__ w1, const float* __restrict__ w2,
                          const float* __restrict__ w3) {
    const float NQ[4] = {3.f, 7.f, 15.f, 31.f};
    int idx = blockIdx.x*blockDim.x + threadIdx.x;
    const int R1 = 4*P*CIN;      // 24576
    const int R2 = 4*P*9;        // 6912
    const int R3 = 4*COUT*P;     // 24576
    if (idx < R1) {
        int j = idx/(P*CIN); int r = idx%(P*CIN); int p=r/CIN; int c=r%CIN;
        float acc = 0.f;
        #pragma unroll
        for (int i=0;i<4;i++){
            int cand = 4*i+j;
            acc += g_probs[cand]*quantw(w1[cand*(P*CIN)+p*CIN+c], NQ[i], g_maxes[cand]);
        }
        float val = acc / NQ[j];                 // fold activation 1/n_j
        float hi  = h16f(val);
        float lo  = (val - hi) * 4096.0f;        // exact *2^12 in fp32
        int K = c*4 + j;                          // k index 0..127
        uint32_t sw = swz((uint32_t)K*2, (uint32_t)p);
        *(unsigned short*)(g_W1img + (size_t)p*256 + sw)          = h16u(hi);
        *(unsigned short*)(g_W1img + 49152 + (size_t)p*256 + sw)  = h16u(lo);
    } else if (idx < R1+R2) {
        int t = idx-R1; int j=t/(P*9); int r=t%(P*9); int p=r/9; int e=r%9;
        float acc = 0.f;
        #pragma unroll
        for (int i=0;i<4;i++){
            int cand = 4*i+j;
            acc += g_probs[16+cand]*quantw(w2[cand*(P*9)+p*9+e], NQ[i], g_maxes[16+cand]);
        }
        g_W2[(j*P+p)*9 + e] = acc / NQ[j];
    } else if (idx < R1+R2+R3) {
        int t = idx-R1-R2; int j=t/(COUT*P); int r=t%(COUT*P); int o=r/P; int p=r%P;
        float acc = 0.f;
        #pragma unroll
        for (int i=0;i<4;i++){
            int cand = 4*i+j;
            acc += g_probs[32+cand]*quantw(w3[cand*(COUT*P)+o*P+p], NQ[i], g_maxes[32+cand]);
        }
        float val = acc / NQ[j];
        float hi  = h16f(val);
        float lo  = (val - hi) * 4096.0f;
        int K = p*4 + j;                 // 0..767
        int kc = K >> 7, kl = K & 127;
        uint32_t sw = swz((uint32_t)kl*2, (uint32_t)o);
        size_t base = (size_t)kc*16384 + (size_t)o*256 + sw;
        *(unsigned short*)(g_W3img + base)        = h16u(hi);
        *(unsigned short*)(g_W3img + base + 8192) = h16u(lo);
    }
}

// ---------------- K3: GEMM1, 256 threads, m=32 tiles, 2-pass fp16 -----------
// (unchanged from the 151us R16 version)
__global__ __launch_bounds__(256, 1) void k_gemm1(const float* __restrict__ x) {
    extern __shared__ __align__(1024) char smem[];
    const uint32_t sb = smem_u32(smem);
    const int tid = threadIdx.x;
    const int wid = tid >> 5, lid = tid & 31;
    const int n0 = blockIdx.x * 128;
    const int b  = n0 >> 10;
    const int s0 = n0 & 1023;
    const uint32_t W_OFF = 32768;

    {
        int c  = tid >> 3;               // input channel 0..31
        int pg = (tid & 7) * 16;         // 16 pixels per thread
        const float* xp = x + ((size_t)(b*CIN + c))*HW + s0 + pg;
        uint32_t bofs = (uint32_t)c * 8;
        #pragma unroll
        for (int u=0; u<4; u++) {
            float4 v4 = *(const float4*)(xp + u*4);
            float vv[4] = {v4.x, v4.y, v4.z, v4.w};
            #pragma unroll
            for (int e=0; e<4; e++) {
                uint32_t row = pg + u*4 + e;
                float v = fminf(fmaxf(vv[e], 0.f), 1.f);
                ushort4 q;
                q.x = h16u(quant_round(v, 3.f));
                q.y = h16u(quant_round(v, 7.f));
                q.z = h16u(quant_round(v, 15.f));
                q.w = h16u(quant_round(v, 31.f));
                *(ushort4*)(smem + row*256 + swz(bofs, row)) = q;
            }
        }
    }
    {
        const float4* src = (const float4*)g_W1img;
        float4* dst = (float4*)(smem + W_OFF);
        #pragma unroll
        for (int it=0; it<24; it++) dst[tid + it*256] = src[tid + it*256];
    }
    __syncthreads();

    float acc[96];
    #pragma unroll
    for (int i=0;i<96;i++) acc[i] = 0.f;

    const int mg = wid & 3, ng = wid >> 2;
    const int m0 = mg * 32;
    const uint32_t swsel = (uint32_t)(lid & 7);
    const uint32_t abase  = sb + (uint32_t)(m0 + (lid & 15)) * 256;
    const uint32_t abase2 = abase + 4096;
    const int halfa = (lid >> 4) & 1;
    const int halfb = (lid >> 3) & 1;
    const uint32_t bbase = sb + W_OFF + (uint32_t)(lid & 7) * 256;

    #pragma unroll 1
    for (int kt = 0; kt < 8; kt++) {
        uint32_t asw = (((uint32_t)(kt*2 + halfa) ^ swsel) << 4);
        uint32_t ah0,ah1,ah2,ah3, bh0,bh1,bh2,bh3;
        ldm_x4(ah0,ah1,ah2,ah3, abase  + asw);
        ldm_x4(bh0,bh1,bh2,bh3, abase2 + asw);
        uint32_t al0 = lo12h(ah0), al1 = lo12h(ah1), al2 = lo12h(ah2), al3 = lo12h(ah3);
        uint32_t bl0 = lo12h(bh0), bl1 = lo12h(bh1), bl2 = lo12h(bh2), bl3 = lo12h(bh3);
        uint32_t bsw = (((uint32_t)(kt*2 + halfb) ^ swsel) << 4);
        #pragma unroll
        for (int i = 0; i < 12; i++) {
            int nt = ng*12 + i;
            uint32_t w0, w1;
            ldm_x2(w0, w1, bbase + nt*2048 + bsw);
            MMA16816(acc + i*4,      ah0,ah1,ah2,ah3, w0,w1);
            MMA16816(acc + 48 + i*4, bh0,bh1,bh2,bh3, w0,w1);
            ldm_x2(w0, w1, bbase + nt*2048 + bsw + 49152);
            MMA16816(acc + i*4,      al0,al1,al2,al3, w0,w1);
            MMA16816(acc + 48 + i*4, bl0,bl1,bl2,bl3, w0,w1);
        }
    }
    __syncthreads();

    float* stage = (float*)smem;          // [192][132]
    {
        int q  = lid & 3;
        int pr = lid >> 2;
        #pragma unroll
        for (int sub = 0; sub < 2; sub++) {
            int col = m0 + sub*16;
            #pragma unroll
            for (int i = 0; i < 12; i++) {
                int ch = (ng*12 + i)*8 + q*2;
                const float* a = acc + sub*48 + i*4;
                stage[(ch  )*132 + col + pr    ] = a[0];
                stage[(ch+1)*132 + col + pr    ] = a[1];
                stage[(ch  )*132 + col + pr + 8] = a[2];
                stage[(ch+1)*132 + col + pr + 8] = a[3];
            }
        }
    }
    __syncthreads();
    if (tid < 192) {
        const float* row = stage + tid*132;
        float s=0.f, q=0.f;
        #pragma unroll 4
        for (int i=0;i<128;i++){ float v=row[i]; s+=v; q=fmaf(v,v,q); }
        atomicAdd(&g_sum1[tid], (double)s);
        atomicAdd(&g_ss1[tid],  (double)q);
    }
    #pragma unroll
    for (int it=0; it<24; it++) {
        int i = tid + it*256;                 // 6144 float4s
        int c = i >> 5, m4 = i & 31;
        float4 v = *(float4*)&stage[c*132 + m4*4];
        *(float4*)&g_out1[(size_t)c*NPIX + n0 + m4*4] = v;
    }
}

// ---------------- K4/K6/K8: BN finalize ------------------------------------
__global__ void k_bnfin(const float* __restrict__ g, const float* __restrict__ bb, int which) {
    int i = threadIdx.x;
    int C = (which==2) ? COUT : P;
    if (i < C) {
        const double* sum = (which==0)?g_sum1:((which==1)?g_sum2:g_sum3);
        const double* ss  = (which==0)?g_ss1 :((which==1)?g_ss2 :g_ss3);
        float* scale = (which==0)?g_scale1:((which==1)?g_scale2:g_scale3);
        float* shift = (which==0)?g_shift1:((which==1)?g_shift2:g_shift3);
        double mean = sum[i] / (double)NPIX;
        double var  = ss[i] / (double)NPIX - mean*mean;
        double sc   = (double)g[i] * rsqrt(var + EPSV);
        scale[i] = (float)sc;
        shift[i] = (float)((double)bb[i] - mean*sc);
    }
}

// ---------------- K5: depthwise 3x3, 2 images per block + BN stats ----------
__global__ __launch_bounds__(256) void k_dw() {
    __shared__ float q4[2][34][36][4];   // j-packed quantized halo, 2 images
    __shared__ float red[16];
    int blk = blockIdx.x;                // grid = P * 128
    int p  = blk >> 7;
    int b0 = (blk & 127) * 2;
    int tid = threadIdx.x;
    const float sc = g_scale1[p], sh = g_shift1[p];
    const float NQ[4] = {3.f,7.f,15.f,31.f};

    for (int i=tid; i<2312; i+=256) {
        int img = (i >= 1156) ? 1 : 0;
        int ii  = i - img*1156;
        int hy = ii/34, hx = ii - hy*34;
        int yy = hy-1, xx = hx-1;
        float4 q = make_float4(0.f,0.f,0.f,0.f);
        if (yy>=0 && yy<32 && xx>=0 && xx<32) {
            const float* plane = g_out1 + (size_t)p*NPIX + (b0+img)*HW;
            float v = plane[yy*32+xx];
            v = fmaf(v, sc, sh);
            v = fminf(fmaxf(v, 0.f), 1.f);
            q.x = quant_round(v, NQ[0]);
            q.y = quant_round(v, NQ[1]);
            q.z = quant_round(v, NQ[2]);
            q.w = quant_round(v, NQ[3]);
        }
        *(float4*)&q4[img][hy][hx][0] = q;
    }
    float w[4][9];
    #pragma unroll
    for (int j=0;j<4;j++)
        #pragma unroll
        for (int e=0;e<9;e++) w[j][e] = g_W2[(j*P+p)*9 + e];
    __syncthreads();

    int oy  = tid >> 3;
    int ox0 = (tid & 7) * 4;
    float rs = 0.f, rq = 0.f;
    #pragma unroll
    for (int img=0; img<2; img++) {
        float accp[4] = {0.f,0.f,0.f,0.f};
        #pragma unroll
        for (int ky=0;ky<3;ky++) {
            float4 v[6];
            #pragma unroll
            for (int xx=0;xx<6;xx++) v[xx] = *(float4*)&q4[img][oy+ky][ox0+xx][0];
            #pragma unroll
            for (int px=0;px<4;px++)
                #pragma unroll
                for (int kx=0;kx<3;kx++) {
                    float4 q = v[px+kx];
                    float ww;
                    ww = w[0][ky*3+kx]; accp[px] = fmaf(ww, q.x, accp[px]);
                    ww = w[1][ky*3+kx]; accp[px] = fmaf(ww, q.y, accp[px]);
                    ww = w[2][ky*3+kx]; accp[px] = fmaf(ww, q.z, accp[px]);
                    ww = w[3][ky*3+kx]; accp[px] = fmaf(ww, q.w, accp[px]);
                }
        }
        float* outp = g_out2 + (size_t)p*NPIX + (b0+img)*HW + oy*32 + ox0;
        *(float4*)outp = make_float4(accp[0],accp[1],accp[2],accp[3]);
        rs += accp[0]+accp[1]+accp[2]+accp[3];
        rq += fmaf(accp[0],accp[0], fmaf(accp[1],accp[1],
              fmaf(accp[2],accp[2], accp[3]*accp[3])));
    }

    #pragma unroll
    for (int o=16;o;o>>=1){ rs += __shfl_xor_sync(0xffffffffu,rs,o);
                            rq += __shfl_xor_sync(0xffffffffu,rq,o); }
    int warp = tid>>5, lane = tid&31;
    if (lane==0){ red[warp]=rs; red[8+warp]=rq; }
    __syncthreads();
    if (tid==0){
        float s=0.f, q=0.f;
        #pragma unroll
        for (int wv=0;wv<8;wv++){ s+=red[wv]; q+=red[8+wv]; }
        atomicAdd(&g_sum2[p], (double)s);
        atomicAdd(&g_ss2[p],  (double)q);
    }
}

// ---------------- K7: GEMM3, K-chunks of 256, software-pipelined ------------
// CTA: D[128 pix, 32 ch] = Aq[128,768] x W3[32,768]^T; 3 chunks of 256 k
// (two 128-k sub-tiles each). Prefetch next chunk's g_out2 into registers
// before the current chunk's mma so DRAM latency overlaps tensor work.
// smem 163840 B: A [0,64K) (2 sub-tiles of 32K) | W3 [64K,160K)
// epilogue stage [32][132] fp32 reuses A region after final sync.
__global__ __launch_bounds__(256, 1) void k_gemm3() {
    extern __shared__ __align__(1024) char smem[];
    const uint32_t sb = smem_u32(smem);
    const int tid = threadIdx.x;
    const int wid = tid >> 5, lid = tid & 31;
    const int n0 = blockIdx.x * 128;
    const int b  = n0 >> 10;
    const int s0 = n0 & 1023;
    const uint32_t W_OFF = 65536;

    // copy all W3 images (98304 B)
    {
        const float4* src = (const float4*)g_W3img;
        float4* dst = (float4*)(smem + W_OFF);
        #pragma unroll
        for (int it=0; it<24; it++) dst[tid + it*256] = src[tid + it*256];
    }

    const int cb  = tid >> 2;          // channel within 64-ch chunk
    const int pg  = (tid & 3) * 32;    // 32 pixels per thread
    const uint32_t aoff = (uint32_t)(cb >> 5) * 32768;   // sub-tile 0/1
    const uint32_t bofs = (uint32_t)(cb & 31) * 8;

    const int mg = wid & 3, ng = wid >> 2;
    const int m0 = mg * 32;
    const uint32_t swsel = (uint32_t)(lid & 7);
    const uint32_t abase = sb + (uint32_t)(m0 + (lid & 15)) * 256;
    const int halfa = (lid >> 4) & 1;
    const int halfb = (lid >> 3) & 1;
    const uint32_t bbase0 = sb + W_OFF + (uint32_t)(lid & 7) * 256;

    float acc[16];                       // [sub 2][nt 2][4]
    #pragma unroll
    for (int i=0;i<16;i++) acc[i] = 0.f;

    // prefetch chunk 0
    float4 vv[8];
    {
        const float* ip = g_out2 + (size_t)cb*NPIX + b*HW + s0 + pg;
        #pragma unroll
        for (int u=0; u<8; u++) vv[u] = *(const float4*)(ip + u*4);
    }

    #pragma unroll 1
    for (int kc=0; kc<3; kc++) {
        if (kc > 0) __syncthreads();     // previous mma done reading A
        // quant + store current chunk (BN + clip + 4-level quant)
        {
            int pch = kc*64 + cb;
            float scl = g_scale2[pch], shf = g_shift2[pch];
            #pragma unroll
            for (int u=0; u<8; u++) {
                float vals[4] = {vv[u].x, vv[u].y, vv[u].z, vv[u].w};
                #pragma unroll
                for (int e=0; e<4; e++) {
                    uint32_t row = pg + u*4 + e;
                    float v = fmaf(vals[e], scl, shf);
                    v = fminf(fmaxf(v, 0.f), 1.f);
                    ushort4 q;
                    q.x = h16u(quant_round(v, 3.f));
                    q.y = h16u(quant_round(v, 7.f));
                    q.z = h16u(quant_round(v, 15.f));
                    q.w = h16u(quant_round(v, 31.f));
                    *(ushort4*)(smem + aoff + row*256 + swz(bofs, row)) = q;
                }
            }
        }
        __syncthreads();                 // A ready (also covers W copy at kc=0)
        // prefetch next chunk (overlaps with mma below)
        if (kc < 2) {
            int pchN = (kc+1)*64 + cb;
            const float* ipN = g_out2 + (size_t)pchN*NPIX + b*HW + s0 + pg;
            #pragma unroll
            for (int u=0; u<8; u++) vv[u] = *(const float4*)(ipN + u*4);
        }
        // mma over the chunk's two 128-k sub-tiles
        #pragma unroll 1
        for (int kt = 0; kt < 16; kt++) {
            int t  = kt >> 3;
            int k8 = kt & 7;
            uint32_t ab  = abase + (uint32_t)t * 32768u;
            uint32_t asw = (((uint32_t)(k8*2 + halfa) ^ swsel) << 4);
            uint32_t ah0,ah1,ah2,ah3, bh0,bh1,bh2,bh3;
            ldm_x4(ah0,ah1,ah2,ah3, ab + asw);
            ldm_x4(bh0,bh1,bh2,bh3, ab + 4096 + asw);
            uint32_t al0 = lo12h(ah0), al1 = lo12h(ah1), al2 = lo12h(ah2), al3 = lo12h(ah3);
            uint32_t bl0 = lo12h(bh0), bl1 = lo12h(bh1), bl2 = lo12h(bh2), bl3 = lo12h(bh3);
            uint32_t bsw = (((uint32_t)(k8*2 + halfb) ^ swsel) << 4);
            uint32_t bbase = bbase0 + (uint32_t)(kc*2 + t) * 16384u;
            #pragma unroll
            for (int i = 0; i < 2; i++) {
                int nt = ng*2 + i;
                uint32_t w0, w1;
                ldm_x2(w0, w1, bbase + nt*2048 + bsw);
                MMA16816(acc + i*4,     ah0,ah1,ah2,ah3, w0,w1);
                MMA16816(acc + 8 + i*4, bh0,bh1,bh2,bh3, w0,w1);
                ldm_x2(w0, w1, bbase + nt*2048 + bsw + 8192);
                MMA16816(acc + i*4,     al0,al1,al2,al3, w0,w1);
                MMA16816(acc + 8 + i*4, bl0,bl1,bl2,bl3, w0,w1);
            }
        }
    }
    __syncthreads();

    // epilogue: acc -> stage[32][132] -> stats + planar STG
    float* stage = (float*)smem;
    {
        int q  = lid & 3;
        int pr = lid >> 2;
        #pragma unroll
        for (int sub = 0; sub < 2; sub++) {
            int col = m0 + sub*16;
            #pragma unroll
            for (int i = 0; i < 2; i++) {
                int ch = (ng*2 + i)*8 + q*2;
                const float* a = acc + sub*8 + i*4;
                stage[(ch  )*132 + col + pr    ] = a[0];
                stage[(ch+1)*132 + col + pr    ] = a[1];
                stage[(ch  )*132 + col + pr + 8] = a[2];
                stage[(ch+1)*132 + col + pr + 8] = a[3];
            }
        }
    }
    __syncthreads();
    if (tid < 32) {
        const float* row = stage + tid*132;
        float s=0.f, q=0.f;
        #pragma unroll 4
        for (int i=0;i<128;i++){ float v=row[i]; s+=v; q=fmaf(v,v,q); }
        atomicAdd(&g_sum3[tid], (double)s);
        atomicAdd(&g_ss3[tid],  (double)q);
    }
    #pragma unroll
    for (int it=0; it<4; it++) {
        int i = tid + it*256;               // 1024 float4s
        int ch = i >> 5, m4 = i & 31;
        float4 v = *(float4*)&stage[ch*132 + m4*4];
        *(float4*)&g_out3[(size_t)ch*NPIX + n0 + m4*4] = v;
    }
}

// ---------------- K9: final  out = bn3(out3) + x ---------------------------
__global__ void k_final(const float* __restrict__ x, float* __restrict__ out) {
    int i = blockIdx.x*blockDim.x + threadIdx.x;     // float4 index
    if (i >= (COUT*NPIX)/4) return;
    int s4 = i & 255;
    int o  = (i >> 8) & 31;
    int b  = i >> 13;
    float4 v  = *(const float4*)&g_out3[(size_t)o*NPIX + b*HW + s4*4];
    float4 xi = ((const float4*)x)[i];
    float sc = g_scale3[o], sh = g_shift3[o];
    float4 r;
    r.x = fmaf(v.x, sc, sh) + xi.x;
    r.y = fmaf(v.y, sc, sh) + xi.y;
    r.z = fmaf(v.z, sc, sh) + xi.z;
    r.w = fmaf(v.w, sc, sh) + xi.w;
    ((float4*)out)[i] = r;
}

// ---------------- launch ----------------------------------------------------
extern "C" void kernel_launch(void* const* d_in, const int* in_sizes, int n_in,
                              void* d_out, int out_size) {
    const float* x  = (const float*)d_in[0];
    const float* w1 = (const float*)d_in[1];
    const float* w2 = (const float*)d_in[2];
    const float* w3 = (const float*)d_in[3];
    const float* p1 = (const float*)d_in[4];
    const float* p2 = (const float*)d_in[5];
    const float* p3 = (const float*)d_in[6];
    const float* g1 = (const float*)d_in[7];
    const float* b1 = (const float*)d_in[8];
    const float* g2 = (const float*)d_in[9];
    const float* b2 = (const float*)d_in[10];
    const float* g3 = (const float*)d_in[11];
    const float* b3 = (const float*)d_in[12];
    float* out = (float*)d_out;

    const int SMEM_G1 = 131072;
    const int SMEM_G3 = 163840;
    cudaFuncSetAttribute(k_gemm1, cudaFuncAttributeMaxDynamicSharedMemorySize, SMEM_G1);
    cudaFuncSetAttribute(k_gemm3, cudaFuncAttributeMaxDynamicSharedMemorySize, SMEM_G3);

    k_init<<<1, 256>>>(p1, p2, p3);
    k_maxes<<<48, 256>>>(w1, w2, w3);
    k_weights<<<(4*P*CIN + 4*P*9 + 4*COUT*P + 255)/256, 256>>>(w1, w2, w3);
    k_gemm1<<<NPIX/128, 256, SMEM_G1>>>(x);
    k_bnfin<<<1, 256>>>(g1, b1, 0);
    k_dw<<<P*128, 256>>>();
    k_bnfin<<<1, 256>>>(g2, b2, 1);
    k_gemm3<<<NPIX/128, 256, SMEM_G3>>>();
    k_bnfin<<<1, 256>>>(g3, b3, 2);
    k_final<<<(COUT*NPIX/4 + 255)/256, 256>>>(x, out);
}